// round 1
// baseline (speedup 1.0000x reference)
#include <cuda_runtime.h>

// LSTM: T=4096, B=2048, I=2, H=4, L=4. Gate order i,f,g,o.
// Mapping: 16 lanes per batch element, lane g = gate row g (i:0-3, f:4-7, g:8-11, o:12-15).
// Each lane holds its weight rows in registers. Skewed layer pipeline:
// one body computes L0(s), L1(s-1), L2(s-2), L3(s-3) independently.

#define TT 4096
#define BB 2048
#define LL 4

__device__ __forceinline__ float ex2f(float x) {
    float y; asm("ex2.approx.f32 %0, %1;" : "=f"(y) : "f"(x)); return y;
}
__device__ __forceinline__ float rcpf(float x) {
    float y; asm("rcp.approx.f32 %0, %1;" : "=f"(y) : "f"(x)); return y;
}

__global__ __launch_bounds__(128) void lstm_kernel(
    const float* __restrict__ x,     // (T, B, 2)
    const float* __restrict__ h0g,   // (L, B, 4)
    const float* __restrict__ c0g,   // (L, B, 4)
    const float* __restrict__ Wih0,  // (16, 2)
    const float* __restrict__ Wr,    // (3, 16, 4)
    const float* __restrict__ Whh,   // (4, 16, 4)
    const float* __restrict__ bih,   // (4, 16)
    const float* __restrict__ bhh,   // (4, 16)
    float* __restrict__ out)         // ys (T,B,4) ++ hT (L,B,4) ++ cT (L,B,4)
{
    const int tid   = threadIdx.x;
    const int g     = tid & 15;          // gate row 0..15
    const int grp   = tid >> 4;          // batch group within block
    const int batch = blockIdx.x * (blockDim.x >> 4) + grp;
    const int j     = g & 3;             // hidden unit index
    const int gt    = g >> 2;            // 0=i,1=f,2=g,3=o

    // ---- weights for this lane's row, in registers ----
    const float w00 = Wih0[g * 2 + 0];
    const float w01 = Wih0[g * 2 + 1];
    float wr[3][4], wh[4][4], bz[4];
#pragma unroll
    for (int m = 0; m < 3; m++)
#pragma unroll
        for (int k = 0; k < 4; k++) wr[m][k] = Wr[(m * 16 + g) * 4 + k];
#pragma unroll
    for (int l = 0; l < 4; l++) {
#pragma unroll
        for (int k = 0; k < 4; k++) wh[l][k] = Whh[(l * 16 + g) * 4 + k];
        bz[l] = bih[l * 16 + g] + bhh[l * 16 + g];
    }

    const bool  isg = (gt == 2);
    const float s1  = isg ? -2.8853900817779268f : -1.4426950408889634f; // -(mult)*log2(e)
    const float m2  = isg ? 2.0f : 1.0f;
    const float a2  = isg ? -1.0f : 0.0f;

    // ---- initial states ----
    float h[4][4];   // h[l][k]: last computed hidden of layer l (replicated per lane)
    float c[4];      // cell value for unit j of layer l (replicated across quads)
#pragma unroll
    for (int l = 0; l < 4; l++) {
        const float4 hv = *reinterpret_cast<const float4*>(h0g + (l * BB + batch) * 4);
        h[l][0] = hv.x; h[l][1] = hv.y; h[l][2] = hv.z; h[l][3] = hv.w;
        c[l] = c0g[(l * BB + batch) * 4 + j];
    }

    float* __restrict__ ys  = out;
    float* __restrict__ hso = out + (size_t)TT * BB * 4;
    float* __restrict__ cso = hso + (size_t)LL * BB * 4;

    // ---- x streaming (prefetch depth 2) ----
    const float* xb = x + batch * 2;
    float2 xa = *reinterpret_cast<const float2*>(xb);                        // x[0]
    float2 xn = *reinterpret_cast<const float2*>(xb + (size_t)BB * 2);       // x[1]

    // activation + state update for one layer (all 16 lanes cooperate)
    auto update = [&](float z, float& cc,
                      float& hv0, float& hv1, float& hv2, float& hv3) {
        float a    = rcpf(1.0f + ex2f(z * s1));
        float gate = fmaf(a, m2, a2);                       // sigmoid or tanh
        float iv = __shfl_sync(0xffffffffu, gate, j,      16);
        float fv = __shfl_sync(0xffffffffu, gate, j + 4,  16);
        float gv = __shfl_sync(0xffffffffu, gate, j + 8,  16);
        float ov = __shfl_sync(0xffffffffu, gate, j + 12, 16);
        cc = fmaf(fv, cc, iv * gv);
        float r  = rcpf(1.0f + ex2f(cc * -2.8853900817779268f));
        float th = fmaf(r, 2.0f, -1.0f);                    // tanh(cc)
        float ho = ov * th;
        hv0 = __shfl_sync(0xffffffffu, ho, 0, 16);
        hv1 = __shfl_sync(0xffffffffu, ho, 1, 16);
        hv2 = __shfl_sync(0xffffffffu, ho, 2, 16);
        hv3 = __shfl_sync(0xffffffffu, ho, 3, 16);
    };

    // One skewed body: L0 at t=s, L1 at s-1, L2 at s-2, L3 at s-3.
    // All pre-activations computed from OLD state first; the 4 updates are independent.
    auto body = [&](int s, bool A0, bool A1, bool A2, bool A3) {
        int tp = s + 2; if (tp > TT - 1) tp = TT - 1;
        float2 xf = *reinterpret_cast<const float2*>(xb + (size_t)tp * BB * 2);

        float z0 = 0.f, z1 = 0.f, z2 = 0.f, z3 = 0.f;
        if (A3) {
            z3 = bz[3];
#pragma unroll
            for (int k = 0; k < 4; k++) z3 = fmaf(wr[2][k], h[2][k], z3);
#pragma unroll
            for (int k = 0; k < 4; k++) z3 = fmaf(wh[3][k], h[3][k], z3);
        }
        if (A2) {
            z2 = bz[2];
#pragma unroll
            for (int k = 0; k < 4; k++) z2 = fmaf(wr[1][k], h[1][k], z2);
#pragma unroll
            for (int k = 0; k < 4; k++) z2 = fmaf(wh[2][k], h[2][k], z2);
        }
        if (A1) {
            z1 = bz[1];
#pragma unroll
            for (int k = 0; k < 4; k++) z1 = fmaf(wr[0][k], h[0][k], z1);
#pragma unroll
            for (int k = 0; k < 4; k++) z1 = fmaf(wh[1][k], h[1][k], z1);
        }
        if (A0) {
            z0 = fmaf(w00, xa.x, fmaf(w01, xa.y, bz[0]));
#pragma unroll
            for (int k = 0; k < 4; k++) z0 = fmaf(wh[0][k], h[0][k], z0);
        }

        if (A3) {
            update(z3, c[3], h[3][0], h[3][1], h[3][2], h[3][3]);
            if (g == 0) {
                *reinterpret_cast<float4*>(ys + ((size_t)(s - 3) * BB + batch) * 4) =
                    make_float4(h[3][0], h[3][1], h[3][2], h[3][3]);
            }
        }
        if (A2) update(z2, c[2], h[2][0], h[2][1], h[2][2], h[2][3]);
        if (A1) update(z1, c[1], h[1][0], h[1][1], h[1][2], h[1][3]);
        if (A0) update(z0, c[0], h[0][0], h[0][1], h[0][2], h[0][3]);

        xa = xn; xn = xf;
    };

    // prologue
    body(0, true, false, false, false);
    body(1, true, true,  false, false);
    body(2, true, true,  true,  false);
    // steady state, all layers active, guards fold away
#pragma unroll 1
    for (int s = 3; s < TT; s++) body(s, true, true, true, true);
    // epilogue (drain)
    body(TT,     false, true,  true,  true);
    body(TT + 1, false, false, true,  true);
    body(TT + 2, false, false, false, true);

    // ---- final hT / cT ----
#pragma unroll
    for (int l = 0; l < 4; l++) {
        if (g == 0) {
            *reinterpret_cast<float4*>(hso + (l * BB + batch) * 4) =
                make_float4(h[l][0], h[l][1], h[l][2], h[l][3]);
        }
        if (gt == 0) {
            cso[(l * BB + batch) * 4 + j] = c[l];
        }
    }
}

extern "C" void kernel_launch(void* const* d_in, const int* in_sizes, int n_in,
                              void* d_out, int out_size) {
    (void)in_sizes; (void)n_in; (void)out_size;
    const float* x    = (const float*)d_in[0];
    const float* h0   = (const float*)d_in[1];
    const float* c0   = (const float*)d_in[2];
    const float* Wih0 = (const float*)d_in[3];
    const float* Wr   = (const float*)d_in[4];
    const float* Whh  = (const float*)d_in[5];
    const float* bih  = (const float*)d_in[6];
    const float* bhh  = (const float*)d_in[7];
    // 128 threads = 8 batch groups per block; 2048/8 = 256 blocks
    lstm_kernel<<<BB / 8, 128>>>(x, h0, c0, Wih0, Wr, Whh, bih, bhh, (float*)d_out);
}